// round 4
// baseline (speedup 1.0000x reference)
#include <cuda_runtime.h>
#include <cstdint>

#define BATCH 16
#define NH 4
#define HEADS (BATCH*NH)      // 64
#define D 64
#define S 1024
#define NELEM (HEADS*D*S)     // 4194304 per tensor

// ---- scratch (device globals; no runtime allocation) ----
__device__ int8_t  g_q8[HEADS*S*D];            // [head][s][d]  4MB
__device__ int8_t  g_k8[HEADS*S*D];            // [head][t][d]  4MB
__device__ int8_t  g_v8[HEADS*D*S];            // [head][d][t]  4MB
__device__ float   g_rden[HEADS*S];            // 1/denominator per row, 256KB
__device__ unsigned g_stat[4];                  // absmax bits: q,k,v ; maxprob bits

// ------------------------------------------------------------------
__global__ void k_init() {
    g_stat[0] = 0u; g_stat[1] = 0u; g_stat[2] = 0u; g_stat[3] = 0u;
}

// ------------------------------------------------------------------
__global__ void k_absmax(const float* __restrict__ q,
                         const float* __restrict__ k,
                         const float* __restrict__ v) {
    const float* p = (blockIdx.y == 0) ? q : ((blockIdx.y == 1) ? k : v);
    const float4* p4 = (const float4*)p;
    const int n4 = NELEM / 4;
    float m = 0.0f;
    for (int i = blockIdx.x * blockDim.x + threadIdx.x; i < n4;
         i += gridDim.x * blockDim.x) {
        float4 x = p4[i];
        m = fmaxf(m, fmaxf(fmaxf(fabsf(x.x), fabsf(x.y)),
                           fmaxf(fabsf(x.z), fabsf(x.w))));
    }
    #pragma unroll
    for (int o = 16; o; o >>= 1) m = fmaxf(m, __shfl_xor_sync(0xffffffffu, m, o));
    __shared__ float sm[8];
    if ((threadIdx.x & 31) == 0) sm[threadIdx.x >> 5] = m;
    __syncthreads();
    if (threadIdx.x == 0) {
        float t = sm[0];
        #pragma unroll
        for (int w = 1; w < 8; w++) t = fmaxf(t, sm[w]);
        atomicMax(&g_stat[blockIdx.y], __float_as_uint(t));
    }
}

// ------------------------------------------------------------------
// Quantize + transpose q/k:  in [head][d][s] (float) -> out [head][s][d] (int8)
__global__ void k_quantT(const float* __restrict__ q, const float* __restrict__ k) {
    const float* src = (blockIdx.z == 0) ? q : k;
    int8_t* dst = (blockIdx.z == 0) ? g_q8 : g_k8;
    const float amax = __uint_as_float(g_stat[blockIdx.z]);
    const float scale = fmaxf(__fdiv_rn(amax, 127.0f), 1e-8f);
    const int head = blockIdx.y;
    const int s0 = blockIdx.x * 64;
    __shared__ int8_t tile[64][68];
    const int t = threadIdx.x;
    #pragma unroll
    for (int i = 0; i < 16; i++) {
        int dd = i * 4 + (t >> 6);
        int ss = t & 63;
        float val = src[((size_t)(head * D + dd)) * S + s0 + ss];
        float r = rintf(__fdiv_rn(val, scale));
        r = fminf(fmaxf(r, -127.0f), 127.0f);
        tile[dd][ss] = (int8_t)r;
    }
    __syncthreads();
    #pragma unroll
    for (int i = 0; i < 4; i++) {
        int ss = i * 16 + (t >> 4);
        int d4 = (t & 15) * 4;
        char4 c;
        c.x = tile[d4 + 0][ss]; c.y = tile[d4 + 1][ss];
        c.z = tile[d4 + 2][ss]; c.w = tile[d4 + 3][ss];
        *(char4*)&dst[((size_t)(head * S + s0 + ss)) * D + d4] = c;
    }
}

// ------------------------------------------------------------------
// Quantize v in-layout: [head][d][t] float -> int8. One warp per half row.
// grid 1024, block 256
__global__ void k_quantV(const float* __restrict__ v) {
    const float amax = __uint_as_float(g_stat[2]);
    const float scale = fmaxf(__fdiv_rn(amax, 127.0f), 1e-8f);
    const int wrp = blockIdx.x * 8 + (threadIdx.x >> 5);   // 0..8191
    const int row = wrp >> 1;
    const int half = wrp & 1;
    const int lane = threadIdx.x & 31;
    const float4* src = (const float4*)(v + (size_t)row * S + half * (S / 2));
    char4* dst = (char4*)(g_v8 + (size_t)row * S + half * (S / 2));
    #pragma unroll
    for (int i = 0; i < 4; i++) {
        int idx = lane + 32 * i;
        float4 x = src[idx];
        char4 c;
        c.x = (int8_t)fminf(fmaxf(rintf(__fdiv_rn(x.x, scale)), -127.0f), 127.0f);
        c.y = (int8_t)fminf(fmaxf(rintf(__fdiv_rn(x.y, scale)), -127.0f), 127.0f);
        c.z = (int8_t)fminf(fmaxf(rintf(__fdiv_rn(x.z, scale)), -127.0f), 127.0f);
        c.w = (int8_t)fminf(fmaxf(rintf(__fdiv_rn(x.w, scale)), -127.0f), 127.0f);
        dst[idx] = c;
    }
}

// ------------------------------------------------------------------
// Phase A: QK (exact int dp4a) + softmax denominator only.
// Writes g_rden[row] and atomicMax global max prob (= rcp(denom)).
// grid (S/32, HEADS), block (32,8)=256
__global__ __launch_bounds__(256, 1) void k_denoms() {
    const int head = blockIdx.y;
    const int s0 = blockIdx.x * 32;
    const int tx = threadIdx.x & 31;
    const int ty = threadIdx.x >> 5;

    __shared__ int Asm[32][17];
    __shared__ int Bsm[512][17];

    const int* qi = (const int*)g_q8;
    const int* ki = (const int*)g_k8;

    int acc[4][32];
    #pragma unroll
    for (int r = 0; r < 4; r++)
        #pragma unroll
        for (int j = 0; j < 32; j++) acc[r][j] = 0;

    for (int idx = threadIdx.x; idx < 32 * 16; idx += 256)
        Asm[idx >> 4][idx & 15] =
            qi[((size_t)(head * S + s0 + (idx >> 4))) * 16 + (idx & 15)];

    #pragma unroll
    for (int tc = 0; tc < 2; tc++) {
        if (tc) __syncthreads();
        for (int idx = threadIdx.x; idx < 512 * 16; idx += 256)
            Bsm[idx >> 4][idx & 15] =
                ki[((size_t)(head * S + tc * 512 + (idx >> 4))) * 16 + (idx & 15)];
        __syncthreads();
        #pragma unroll
        for (int kk = 0; kk < 16; kk++) {
            int a0 = Asm[ty * 4 + 0][kk];
            int a1 = Asm[ty * 4 + 1][kk];
            int a2 = Asm[ty * 4 + 2][kk];
            int a3 = Asm[ty * 4 + 3][kk];
            #pragma unroll
            for (int j = 0; j < 16; j++) {
                int bb = Bsm[tx + 32 * j][kk];
                acc[0][tc * 16 + j] = __dp4a(bb, a0, acc[0][tc * 16 + j]);
                acc[1][tc * 16 + j] = __dp4a(bb, a1, acc[1][tc * 16 + j]);
                acc[2][tc * 16 + j] = __dp4a(bb, a2, acc[2][tc * 16 + j]);
                acc[3][tc * 16 + j] = __dp4a(bb, a3, acc[3][tc * 16 + j]);
            }
        }
    }

    const float sq = fmaxf(__fdiv_rn(__uint_as_float(g_stat[0]), 127.0f), 1e-8f);
    const float sk = fmaxf(__fdiv_rn(__uint_as_float(g_stat[1]), 127.0f), 1e-8f);
    const float mult = sq * sk * 0.125f;

    #pragma unroll
    for (int ri = 0; ri < 4; ri++) {
        const int row = ty * 4 + ri;
        float m = -3.4e38f;
        #pragma unroll
        for (int jj = 0; jj < 32; jj++) {
            float l = (float)acc[ri][jj] * mult;
            acc[ri][jj] = __float_as_int(l);
            m = fmaxf(m, l);
        }
        #pragma unroll
        for (int o = 16; o; o >>= 1) m = fmaxf(m, __shfl_xor_sync(0xffffffffu, m, o));
        float ssum = 0.0f;
        #pragma unroll
        for (int jj = 0; jj < 32; jj++)
            ssum += expf(__int_as_float(acc[ri][jj]) - m);
        #pragma unroll
        for (int o = 16; o; o >>= 1) ssum += __shfl_xor_sync(0xffffffffu, ssum, o);
        const float rden = __frcp_rn(ssum);   // == max prob of this row
        if (tx == 0) {
            g_rden[head * S + s0 + row] = rden;
            atomicMax(&g_stat[3], __float_as_uint(rden));
        }
    }
}

// ------------------------------------------------------------------
// Phase B (fused): recompute QK logits (bit-identical), softmax probs using
// stored rden, double-quantize via 256-entry table, PV dp4a, epilogue.
// grid (S/32, HEADS), block (32,8)=256
#define P_STRIDE 1040   // bytes per Psm row (= 260 ints, conflict-free & 16B-aligned)
__global__ __launch_bounds__(256, 1) void k_fused(float* __restrict__ out) {
    const int head = blockIdx.y;
    const int s0 = blockIdx.x * 32;
    const int tid = threadIdx.x;
    const int tx = tid & 31;
    const int ty = tid >> 5;

    // QK staging (Asm+Bsm = 36992B) aliased with quantized-P tile (32*1040=33280B)
    __shared__ __align__(16) char smem_raw[36992];
    __shared__ __align__(16) int Vsm[64][36];   // 9216B
    __shared__ unsigned char k2tab[256];

    int (*Asm)[17] = (int(*)[17])smem_raw;
    int (*Bsm)[17] = (int(*)[17])(smem_raw + 32 * 17 * 4);
    char* Psm = smem_raw;

    // ---- scales + double-quant table ----
    const float maxp = __uint_as_float(g_stat[3]);
    const float s1 = fmaxf(__fdiv_rn(maxp, 255.0f), 1e-8f);
    const float m2v = 255.0f * s1;
    const float s2 = fmaxf(__fdiv_rn(m2v, 127.0f), 1e-8f);
    const float sv = fmaxf(__fdiv_rn(__uint_as_float(g_stat[2]), 127.0f), 1e-8f);
    if (tid < 256) {
        float cq = (float)tid * s1;
        float k2 = fminf(fmaxf(rintf(__fdiv_rn(cq, s2)), 0.0f), 127.0f);
        k2tab[tid] = (unsigned char)(int)k2;
    }

    const int* qi = (const int*)g_q8;
    const int* ki = (const int*)g_k8;

    int acc[4][32];
    #pragma unroll
    for (int r = 0; r < 4; r++)
        #pragma unroll
        for (int j = 0; j < 32; j++) acc[r][j] = 0;

    for (int idx = tid; idx < 32 * 16; idx += 256)
        Asm[idx >> 4][idx & 15] =
            qi[((size_t)(head * S + s0 + (idx >> 4))) * 16 + (idx & 15)];

    #pragma unroll
    for (int tc = 0; tc < 2; tc++) {
        if (tc) __syncthreads();
        for (int idx = tid; idx < 512 * 16; idx += 256)
            Bsm[idx >> 4][idx & 15] =
                ki[((size_t)(head * S + tc * 512 + (idx >> 4))) * 16 + (idx & 15)];
        __syncthreads();
        #pragma unroll
        for (int kk = 0; kk < 16; kk++) {
            int a0 = Asm[ty * 4 + 0][kk];
            int a1 = Asm[ty * 4 + 1][kk];
            int a2 = Asm[ty * 4 + 2][kk];
            int a3 = Asm[ty * 4 + 3][kk];
            #pragma unroll
            for (int j = 0; j < 16; j++) {
                int bb = Bsm[tx + 32 * j][kk];
                acc[0][tc * 16 + j] = __dp4a(bb, a0, acc[0][tc * 16 + j]);
                acc[1][tc * 16 + j] = __dp4a(bb, a1, acc[1][tc * 16 + j]);
                acc[2][tc * 16 + j] = __dp4a(bb, a2, acc[2][tc * 16 + j]);
                acc[3][tc * 16 + j] = __dp4a(bb, a3, acc[3][tc * 16 + j]);
            }
        }
    }

    const float sq = fmaxf(__fdiv_rn(__uint_as_float(g_stat[0]), 127.0f), 1e-8f);
    const float sk = fmaxf(__fdiv_rn(__uint_as_float(g_stat[1]), 127.0f), 1e-8f);
    const float mult = sq * sk * 0.125f;

    __syncthreads();   // everyone done reading Asm/Bsm before Psm overwrites

    // ---- softmax + double-quantize into Psm (int8) ----
    #pragma unroll
    for (int ri = 0; ri < 4; ri++) {
        const int row = ty * 4 + ri;
        float m = -3.4e38f;
        #pragma unroll
        for (int jj = 0; jj < 32; jj++) {
            float l = (float)acc[ri][jj] * mult;
            acc[ri][jj] = __float_as_int(l);
            m = fmaxf(m, l);
        }
        #pragma unroll
        for (int o = 16; o; o >>= 1) m = fmaxf(m, __shfl_xor_sync(0xffffffffu, m, o));
        const float rden = g_rden[head * S + s0 + row];
        #pragma unroll
        for (int jj = 0; jj < 32; jj++) {
            float p = expf(__int_as_float(acc[ri][jj]) - m) * rden;
            float k1 = fminf(fmaxf(rintf(__fdiv_rn(p, s1)), 0.0f), 255.0f);
            int col = (jj >> 4) * 512 + (jj & 15) * 32 + tx;
            Psm[row * P_STRIDE + col] = (char)k2tab[(int)k1];
        }
    }

    // ---- PV: P(int8, smem) x V(int8, gmem-staged) with dp4a ----
    int acc2[8];
    #pragma unroll
    for (int b = 0; b < 8; b++) acc2[b] = 0;
    const int* vi = (const int*)g_v8;

    for (int ch = 0; ch < 8; ch++) {
        __syncthreads();
        for (int idx = tid; idx < 2048; idx += 256) {
            int r = idx >> 5, c = idx & 31;
            Vsm[r][c] = vi[((size_t)(head * D + r)) * 256 + ch * 32 + c];
        }
        __syncthreads();
        #pragma unroll
        for (int g = 0; g < 8; g++) {
            int4 pv = *(const int4*)(Psm + tx * P_STRIDE + ch * 128 + g * 16);
            #pragma unroll
            for (int dj = 0; dj < 8; dj++) {
                int4 vv = *(const int4*)(&Vsm[ty + 8 * dj][g * 4]);
                acc2[dj] = __dp4a(pv.x, vv.x, acc2[dj]);
                acc2[dj] = __dp4a(pv.y, vv.y, acc2[dj]);
                acc2[dj] = __dp4a(pv.z, vv.z, acc2[dj]);
                acc2[dj] = __dp4a(pv.w, vv.w, acc2[dj]);
            }
        }
    }

    const float fs = s2 * sv;
    #pragma unroll
    for (int dj = 0; dj < 8; dj++) {
        int dd = ty + 8 * dj;
        out[((size_t)(head * D + dd)) * S + s0 + tx] = (float)acc2[dj] * fs;
    }
}

// ------------------------------------------------------------------
extern "C" void kernel_launch(void* const* d_in, const int* in_sizes, int n_in,
                              void* d_out, int out_size) {
    (void)in_sizes; (void)n_in; (void)out_size;
    const float* q = (const float*)d_in[0];
    const float* k = (const float*)d_in[1];
    const float* v = (const float*)d_in[2];
    float* out = (float*)d_out;

    k_init<<<1, 1>>>();
    k_absmax<<<dim3(148, 3), 256>>>(q, k, v);
    k_quantT<<<dim3(S / 64, HEADS, 2), 256>>>(q, k);
    k_quantV<<<1024, 256>>>(v);
    k_denoms<<<dim3(S / 32, HEADS), 256>>>();
    k_fused<<<dim3(S / 32, HEADS), 256>>>(out);
}

// round 7
// speedup vs baseline: 2.0456x; 2.0456x over previous
#include <cuda_runtime.h>
#include <cstdint>

#define BATCH 16
#define NH 4
#define HEADS (BATCH*NH)      // 64
#define D 64
#define S 1024
#define NELEM (HEADS*D*S)     // 4194304 per tensor

// ---- scratch (device globals; no runtime allocation) ----
__device__ int8_t  g_q8[HEADS*S*D];            // [head][s][d]  4MB
__device__ int8_t  g_k8[HEADS*S*D];            // [head][t][d]  4MB
__device__ int8_t  g_v8[HEADS*D*S];            // [head][d][t]  4MB
__device__ float   g_rden[HEADS*S];            // 1/denominator per row
__device__ float   g_rmax[HEADS*S];            // row max logit
__device__ unsigned g_stat[4];                  // absmax bits: q,k,v ; maxprob bits

// ------------------------------------------------------------------
__device__ __forceinline__ void imma(int* c, const int* a, int b0, int b1) {
    asm volatile(
        "mma.sync.aligned.m16n8k32.row.col.s32.s8.s8.s32 "
        "{%0,%1,%2,%3}, {%4,%5,%6,%7}, {%8,%9}, {%0,%1,%2,%3};\n"
        : "+r"(c[0]), "+r"(c[1]), "+r"(c[2]), "+r"(c[3])
        : "r"(a[0]), "r"(a[1]), "r"(a[2]), "r"(a[3]), "r"(b0), "r"(b1));
}

// ------------------------------------------------------------------
__global__ void k_init() {
    g_stat[0] = 0u; g_stat[1] = 0u; g_stat[2] = 0u; g_stat[3] = 0u;
}

// ------------------------------------------------------------------
__global__ void k_absmax(const float* __restrict__ q,
                         const float* __restrict__ k,
                         const float* __restrict__ v) {
    const float* p = (blockIdx.y == 0) ? q : ((blockIdx.y == 1) ? k : v);
    const float4* p4 = (const float4*)p;
    const int n4 = NELEM / 4;
    float m = 0.0f;
    for (int i = blockIdx.x * blockDim.x + threadIdx.x; i < n4;
         i += gridDim.x * blockDim.x) {
        float4 x = p4[i];
        m = fmaxf(m, fmaxf(fmaxf(fabsf(x.x), fabsf(x.y)),
                           fmaxf(fabsf(x.z), fabsf(x.w))));
    }
    #pragma unroll
    for (int o = 16; o; o >>= 1) m = fmaxf(m, __shfl_xor_sync(0xffffffffu, m, o));
    __shared__ float sm[8];
    if ((threadIdx.x & 31) == 0) sm[threadIdx.x >> 5] = m;
    __syncthreads();
    if (threadIdx.x == 0) {
        float t = sm[0];
        #pragma unroll
        for (int w = 1; w < 8; w++) t = fmaxf(t, sm[w]);
        atomicMax(&g_stat[blockIdx.y], __float_as_uint(t));
    }
}

// ------------------------------------------------------------------
// Quantize + transpose q/k:  in [head][d][s] (float) -> out [head][s][d] (int8)
__global__ void k_quantT(const float* __restrict__ q, const float* __restrict__ k) {
    const float* src = (blockIdx.z == 0) ? q : k;
    int8_t* dst = (blockIdx.z == 0) ? g_q8 : g_k8;
    const float amax = __uint_as_float(g_stat[blockIdx.z]);
    const float scale = fmaxf(__fdiv_rn(amax, 127.0f), 1e-8f);
    const int head = blockIdx.y;
    const int s0 = blockIdx.x * 64;
    __shared__ int8_t tile[64][68];
    const int t = threadIdx.x;
    #pragma unroll
    for (int i = 0; i < 16; i++) {
        int dd = i * 4 + (t >> 6);
        int ss = t & 63;
        float val = src[((size_t)(head * D + dd)) * S + s0 + ss];
        float r = rintf(__fdiv_rn(val, scale));
        r = fminf(fmaxf(r, -127.0f), 127.0f);
        tile[dd][ss] = (int8_t)r;
    }
    __syncthreads();
    #pragma unroll
    for (int i = 0; i < 4; i++) {
        int ss = i * 16 + (t >> 4);
        int d4 = (t & 15) * 4;
        char4 c;
        c.x = tile[d4 + 0][ss]; c.y = tile[d4 + 1][ss];
        c.z = tile[d4 + 2][ss]; c.w = tile[d4 + 3][ss];
        *(char4*)&dst[((size_t)(head * S + s0 + ss)) * D + d4] = c;
    }
}

// ------------------------------------------------------------------
__global__ void k_quantV(const float* __restrict__ v) {
    const float amax = __uint_as_float(g_stat[2]);
    const float scale = fmaxf(__fdiv_rn(amax, 127.0f), 1e-8f);
    const int wrp = blockIdx.x * 8 + (threadIdx.x >> 5);   // 0..8191
    const int row = wrp >> 1;
    const int half = wrp & 1;
    const int lane = threadIdx.x & 31;
    const float4* src = (const float4*)(v + (size_t)row * S + half * (S / 2));
    char4* dst = (char4*)(g_v8 + (size_t)row * S + half * (S / 2));
    #pragma unroll
    for (int i = 0; i < 4; i++) {
        int idx = lane + 32 * i;
        float4 x = src[idx];
        char4 c;
        c.x = (int8_t)fminf(fmaxf(rintf(__fdiv_rn(x.x, scale)), -127.0f), 127.0f);
        c.y = (int8_t)fminf(fmaxf(rintf(__fdiv_rn(x.y, scale)), -127.0f), 127.0f);
        c.z = (int8_t)fminf(fmaxf(rintf(__fdiv_rn(x.z, scale)), -127.0f), 127.0f);
        c.w = (int8_t)fminf(fmaxf(rintf(__fdiv_rn(x.w, scale)), -127.0f), 127.0f);
        dst[idx] = c;
    }
}

// ------------------------------------------------------------------
// Phase A: QK via IMMA + online softmax; store rden (=max prob) and row max.
// grid (8, 64), block 256 (8 warps x 16 rows = 128 Q rows per CTA)
__global__ __launch_bounds__(256) void k_phaseA() {
    const int head = blockIdx.y;
    const int s_blk = blockIdx.x * 128;
    const int tid = threadIdx.x;
    const int w = tid >> 5, lane = tid & 31;
    const int qr = lane >> 2, ql = lane & 3;

    __shared__ __align__(16) int Ksm[128 * 20];   // stride 80B, conflict-free

    // A fragments: 16 Q rows of this warp, k=64 in 2 ksteps
    int aq[2][4];
    {
        const int8_t* qb = g_q8 + ((size_t)(head * S + s_blk + w * 16)) * 64;
        #pragma unroll
        for (int ks = 0; ks < 2; ks++) {
            aq[ks][0] = *(const int*)(qb + qr * 64 + ks * 32 + ql * 4);
            aq[ks][1] = *(const int*)(qb + (qr + 8) * 64 + ks * 32 + ql * 4);
            aq[ks][2] = *(const int*)(qb + qr * 64 + ks * 32 + 16 + ql * 4);
            aq[ks][3] = *(const int*)(qb + (qr + 8) * 64 + ks * 32 + 16 + ql * 4);
        }
    }
    const float sq = fmaxf(__fdiv_rn(__uint_as_float(g_stat[0]), 127.0f), 1e-8f);
    const float sk = fmaxf(__fdiv_rn(__uint_as_float(g_stat[1]), 127.0f), 1e-8f);
    const float mult = sq * sk * 0.125f;

    float m0 = -3.4e38f, m1 = -3.4e38f, sum0 = 0.0f, sum1 = 0.0f;

    for (int ch = 0; ch < 8; ch++) {
        __syncthreads();
        const int* src = (const int*)(g_k8 + ((size_t)(head * S + ch * 128)) * 64);
        for (int i = tid; i < 2048; i += 256)
            Ksm[(i >> 4) * 20 + (i & 15)] = src[i];
        __syncthreads();

        int qa[16][4];
        #pragma unroll
        for (int nt = 0; nt < 16; nt++)
            qa[nt][0] = qa[nt][1] = qa[nt][2] = qa[nt][3] = 0;
        #pragma unroll
        for (int ks = 0; ks < 2; ks++) {
            #pragma unroll
            for (int nt = 0; nt < 16; nt++) {
                int base = (nt * 8 + qr) * 20 + ks * 8 + ql;
                imma(qa[nt], aq[ks], Ksm[base], Ksm[base + 4]);
            }
        }
        // ints -> float logits (exact: |acc| < 2^24), chunk max
        float cm0 = -3.4e38f, cm1 = -3.4e38f;
        #pragma unroll
        for (int nt = 0; nt < 16; nt++) {
            float l0 = (float)qa[nt][0] * mult; qa[nt][0] = __float_as_int(l0);
            float l1 = (float)qa[nt][1] * mult; qa[nt][1] = __float_as_int(l1);
            float l2 = (float)qa[nt][2] * mult; qa[nt][2] = __float_as_int(l2);
            float l3 = (float)qa[nt][3] * mult; qa[nt][3] = __float_as_int(l3);
            cm0 = fmaxf(cm0, fmaxf(l0, l1));
            cm1 = fmaxf(cm1, fmaxf(l2, l3));
        }
        cm0 = fmaxf(cm0, __shfl_xor_sync(0xffffffffu, cm0, 1));
        cm0 = fmaxf(cm0, __shfl_xor_sync(0xffffffffu, cm0, 2));
        cm1 = fmaxf(cm1, __shfl_xor_sync(0xffffffffu, cm1, 1));
        cm1 = fmaxf(cm1, __shfl_xor_sync(0xffffffffu, cm1, 2));
        float nm0 = fmaxf(m0, cm0), nm1 = fmaxf(m1, cm1);
        sum0 *= expf(m0 - nm0);
        sum1 *= expf(m1 - nm1);
        m0 = nm0; m1 = nm1;
        #pragma unroll
        for (int nt = 0; nt < 16; nt++) {
            sum0 += expf(__int_as_float(qa[nt][0]) - m0);
            sum0 += expf(__int_as_float(qa[nt][1]) - m0);
            sum1 += expf(__int_as_float(qa[nt][2]) - m1);
            sum1 += expf(__int_as_float(qa[nt][3]) - m1);
        }
    }
    sum0 += __shfl_xor_sync(0xffffffffu, sum0, 1);
    sum0 += __shfl_xor_sync(0xffffffffu, sum0, 2);
    sum1 += __shfl_xor_sync(0xffffffffu, sum1, 1);
    sum1 += __shfl_xor_sync(0xffffffffu, sum1, 2);
    const float rd0 = __frcp_rn(sum0);
    const float rd1 = __frcp_rn(sum1);
    if (ql == 0) {
        int r = head * S + s_blk + w * 16 + qr;
        g_rden[r] = rd0; g_rden[r + 8] = rd1;
        g_rmax[r] = m0;  g_rmax[r + 8] = m1;
    }
    float wm = fmaxf(rd0, rd1);
    wm = fmaxf(wm, __shfl_xor_sync(0xffffffffu, wm, 4));
    wm = fmaxf(wm, __shfl_xor_sync(0xffffffffu, wm, 8));
    wm = fmaxf(wm, __shfl_xor_sync(0xffffffffu, wm, 16));
    if (lane == 0) atomicMax(&g_stat[3], __float_as_uint(wm));
}

// ------------------------------------------------------------------
// Phase B: recompute QK (IMMA, identical ints), softmax via stored m/rden,
// table double-quant -> smem P (s8) -> PV IMMA, coalesced epilogue.
// grid (8, 64), block 256
#define SM_KS 0          // 128*20 ints (10240 B)
#define SM_VS 10240      // 64*36 ints  (9216 B)
#define SM_PS 19456      // 8 warps * 2304 B  (16 rows x 144 B)
#define SM_TOT 37888     // Osm (64*132 floats = 33792 B) aliases from 0
__global__ __launch_bounds__(256) void k_phaseB(float* __restrict__ out) {
    __shared__ __align__(16) char sm[SM_TOT];
    __shared__ unsigned char k2tab[256];

    const int head = blockIdx.y;
    const int s_blk = blockIdx.x * 128;
    const int tid = threadIdx.x;
    const int w = tid >> 5, lane = tid & 31;
    const int qr = lane >> 2, ql = lane & 3;

    const float maxp = __uint_as_float(g_stat[3]);
    const float s1 = fmaxf(__fdiv_rn(maxp, 255.0f), 1e-8f);
    const float s2 = fmaxf(__fdiv_rn(255.0f * s1, 127.0f), 1e-8f);
    const float sv = fmaxf(__fdiv_rn(__uint_as_float(g_stat[2]), 127.0f), 1e-8f);
    const float r1s = __fdiv_rn(1.0f, s1);
    if (tid < 256) {
        float cq = (float)tid * s1;
        float k2 = fminf(fmaxf(rintf(__fdiv_rn(cq, s2)), 0.0f), 127.0f);
        k2tab[tid] = (unsigned char)(int)k2;
    }

    int aq[2][4];
    {
        const int8_t* qb = g_q8 + ((size_t)(head * S + s_blk + w * 16)) * 64;
        #pragma unroll
        for (int ks = 0; ks < 2; ks++) {
            aq[ks][0] = *(const int*)(qb + qr * 64 + ks * 32 + ql * 4);
            aq[ks][1] = *(const int*)(qb + (qr + 8) * 64 + ks * 32 + ql * 4);
            aq[ks][2] = *(const int*)(qb + qr * 64 + ks * 32 + 16 + ql * 4);
            aq[ks][3] = *(const int*)(qb + (qr + 8) * 64 + ks * 32 + 16 + ql * 4);
        }
    }
    const float sq = fmaxf(__fdiv_rn(__uint_as_float(g_stat[0]), 127.0f), 1e-8f);
    const float sk = fmaxf(__fdiv_rn(__uint_as_float(g_stat[1]), 127.0f), 1e-8f);
    const float mult = sq * sk * 0.125f;

    const int rbase = head * S + s_blk + w * 16 + qr;
    const float m_lo = g_rmax[rbase],     m_hi = g_rmax[rbase + 8];
    const float rd_lo = g_rden[rbase],    rd_hi = g_rden[rbase + 8];

    int* KsmI = (int*)(sm + SM_KS);
    int* VsmI = (int*)(sm + SM_VS);
    char* PsmW = sm + SM_PS + w * 2304;

    int pacc[8][4];
    #pragma unroll
    for (int nt = 0; nt < 8; nt++)
        pacc[nt][0] = pacc[nt][1] = pacc[nt][2] = pacc[nt][3] = 0;

    const int* ksrc0 = (const int*)(g_k8 + ((size_t)head * S) * 64);
    const int* vsrc0 = (const int*)g_v8 + head * (D * S / 4);

    for (int ch = 0; ch < 8; ch++) {
        __syncthreads();
        const int* ks_src = ksrc0 + ch * 128 * 16;
        for (int i = tid; i < 2048; i += 256)
            KsmI[(i >> 4) * 20 + (i & 15)] = ks_src[i];
        for (int i = tid; i < 2048; i += 256) {
            int dd = i >> 5, wd = i & 31;
            VsmI[dd * 36 + wd] = vsrc0[dd * 256 + ch * 32 + wd];
        }
        __syncthreads();

        // ---- QK ----
        int qa[16][4];
        #pragma unroll
        for (int nt = 0; nt < 16; nt++)
            qa[nt][0] = qa[nt][1] = qa[nt][2] = qa[nt][3] = 0;
        #pragma unroll
        for (int ks = 0; ks < 2; ks++) {
            #pragma unroll
            for (int nt = 0; nt < 16; nt++) {
                int base = (nt * 8 + qr) * 20 + ks * 8 + ql;
                imma(qa[nt], aq[ks], KsmI[base], KsmI[base + 4]);
            }
        }
        // ---- softmax + double-quant into Psm ----
        #pragma unroll
        for (int nt = 0; nt < 16; nt++) {
            float p0 = expf((float)qa[nt][0] * mult - m_lo) * rd_lo;
            float p1 = expf((float)qa[nt][1] * mult - m_lo) * rd_lo;
            float p2 = expf((float)qa[nt][2] * mult - m_hi) * rd_hi;
            float p3 = expf((float)qa[nt][3] * mult - m_hi) * rd_hi;
            int i0 = (int)fminf(fmaxf(rintf(p0 * r1s), 0.0f), 255.0f);
            int i1 = (int)fminf(fmaxf(rintf(p1 * r1s), 0.0f), 255.0f);
            int i2 = (int)fminf(fmaxf(rintf(p2 * r1s), 0.0f), 255.0f);
            int i3 = (int)fminf(fmaxf(rintf(p3 * r1s), 0.0f), 255.0f);
            int col = nt * 8 + ql * 2;
            *(uint16_t*)(PsmW + qr * 144 + col) =
                (uint16_t)(k2tab[i0] | ((uint16_t)k2tab[i1] << 8));
            *(uint16_t*)(PsmW + (qr + 8) * 144 + col) =
                (uint16_t)(k2tab[i2] | ((uint16_t)k2tab[i3] << 8));
        }
        __syncwarp();
        // ---- PV ----
        #pragma unroll
        for (int ks = 0; ks < 4; ks++) {
            int pa[4];
            pa[0] = *(const int*)(PsmW + qr * 144 + ks * 32 + ql * 4);
            pa[1] = *(const int*)(PsmW + (qr + 8) * 144 + ks * 32 + ql * 4);
            pa[2] = *(const int*)(PsmW + qr * 144 + ks * 32 + 16 + ql * 4);
            pa[3] = *(const int*)(PsmW + (qr + 8) * 144 + ks * 32 + 16 + ql * 4);
            #pragma unroll
            for (int nt = 0; nt < 8; nt++) {
                int base = (nt * 8 + qr) * 36 + ks * 8 + ql;
                imma(pacc[nt], pa, VsmI[base], VsmI[base + 4]);
            }
        }
    }

    // ---- epilogue: smem transpose then coalesced store ----
    __syncthreads();
    float* Osm = (float*)sm;
    const float fs = s2 * sv;
    #pragma unroll
    for (int nt = 0; nt < 8; nt++) {
        int d0 = nt * 8 + ql * 2;
        int s_lo = w * 16 + qr;
        Osm[d0 * 132 + s_lo]            = (float)pacc[nt][0] * fs;
        Osm[(d0 + 1) * 132 + s_lo]      = (float)pacc[nt][1] * fs;
        Osm[d0 * 132 + s_lo + 8]        = (float)pacc[nt][2] * fs;
        Osm[(d0 + 1) * 132 + s_lo + 8]  = (float)pacc[nt][3] * fs;
    }
    __syncthreads();
    int dd = tid >> 2;
    int sseg = (tid & 3) * 32;
    float* orow = out + ((size_t)(head * D + dd)) * S + s_blk + sseg;
    #pragma unroll
    for (int i = 0; i < 8; i++)
        *(float4*)(orow + i * 4) = *(float4*)&Osm[dd * 132 + sseg + i * 4];
}

// ------------------------------------------------------------------
extern "C" void kernel_launch(void* const* d_in, const int* in_sizes, int n_in,
                              void* d_out, int out_size) {
    (void)in_sizes; (void)n_in; (void)out_size;
    const float* q = (const float*)d_in[0];
    const float* k = (const float*)d_in[1];
    const float* v = (const float*)d_in[2];
    float* out = (float*)d_out;

    k_init<<<1, 1>>>();
    k_absmax<<<dim3(148, 3), 256>>>(q, k, v);
    k_quantT<<<dim3(S / 64, HEADS, 2), 256>>>(q, k);
    k_quantV<<<1024, 256>>>(v);
    k_phaseA<<<dim3(8, HEADS), 256>>>();
    k_phaseB<<<dim3(8, HEADS), 256>>>(out);
}

// round 9
// speedup vs baseline: 2.1592x; 1.0555x over previous
#include <cuda_runtime.h>
#include <cstdint>

#define BATCH 16
#define NH 4
#define HEADS (BATCH*NH)      // 64
#define D 64
#define S 1024
#define NELEM (HEADS*D*S)     // 4194304 per tensor

// ---- scratch (device globals; no runtime allocation) ----
__device__ int8_t  g_q8[HEADS*S*D];            // [head][s][d]  4MB
__device__ int8_t  g_k8[HEADS*S*D];            // [head][t][d]  4MB
__device__ int8_t  g_v8[HEADS*D*S];            // [head][d][t]  4MB
__device__ float   g_rden[HEADS*S];            // 1/denominator per row
__device__ float   g_rmax[HEADS*S];            // row max logit
__device__ unsigned g_stat[4];                  // absmax bits: q,k,v ; maxprob bits

// ------------------------------------------------------------------
__device__ __forceinline__ void imma(int* c, const int* a, int b0, int b1) {
    asm volatile(
        "mma.sync.aligned.m16n8k32.row.col.s32.s8.s8.s32 "
        "{%0,%1,%2,%3}, {%4,%5,%6,%7}, {%8,%9}, {%0,%1,%2,%3};\n"
        : "+r"(c[0]), "+r"(c[1]), "+r"(c[2]), "+r"(c[3])
        : "r"(a[0]), "r"(a[1]), "r"(a[2]), "r"(a[3]), "r"(b0), "r"(b1));
}

// ------------------------------------------------------------------
__global__ void k_init() {
    g_stat[0] = 0u; g_stat[1] = 0u; g_stat[2] = 0u; g_stat[3] = 0u;
}

// ------------------------------------------------------------------
__global__ void k_absmax(const float* __restrict__ q,
                         const float* __restrict__ k,
                         const float* __restrict__ v) {
    const float* p = (blockIdx.y == 0) ? q : ((blockIdx.y == 1) ? k : v);
    const float4* p4 = (const float4*)p;
    const int n4 = NELEM / 4;
    float m = 0.0f;
    for (int i = blockIdx.x * blockDim.x + threadIdx.x; i < n4;
         i += gridDim.x * blockDim.x) {
        float4 x = p4[i];
        m = fmaxf(m, fmaxf(fmaxf(fabsf(x.x), fabsf(x.y)),
                           fmaxf(fabsf(x.z), fabsf(x.w))));
    }
    #pragma unroll
    for (int o = 16; o; o >>= 1) m = fmaxf(m, __shfl_xor_sync(0xffffffffu, m, o));
    __shared__ float sm[8];
    if ((threadIdx.x & 31) == 0) sm[threadIdx.x >> 5] = m;
    __syncthreads();
    if (threadIdx.x == 0) {
        float t = sm[0];
        #pragma unroll
        for (int w = 1; w < 8; w++) t = fmaxf(t, sm[w]);
        atomicMax(&g_stat[blockIdx.y], __float_as_uint(t));
    }
}

// ------------------------------------------------------------------
// One launch for all quantization.
// z=0: Q transpose-quant, z=1: K transpose-quant, z=2: V in-layout quant.
// grid (16, 64, 3), block 256
__global__ void k_quant(const float* __restrict__ q, const float* __restrict__ k,
                        const float* __restrict__ v) {
    const int z = blockIdx.z;
    __shared__ int8_t tile[64][68];
    const int t = threadIdx.x;

    if (z == 2) {   // ---- V: [head][d][t] float -> int8, same layout ----
        const float amax = __uint_as_float(g_stat[2]);
        const float scale = fmaxf(__fdiv_rn(amax, 127.0f), 1e-8f);
        const int wrp = (blockIdx.y * 16 + blockIdx.x) * 8 + (t >> 5);  // 0..8191
        const int row = wrp >> 1;
        const int half = wrp & 1;
        const int lane = t & 31;
        const float4* src = (const float4*)(v + (size_t)row * S + half * (S / 2));
        char4* dst = (char4*)(g_v8 + (size_t)row * S + half * (S / 2));
        #pragma unroll
        for (int i = 0; i < 4; i++) {
            int idx = lane + 32 * i;
            float4 x = src[idx];
            char4 c;
            c.x = (int8_t)fminf(fmaxf(rintf(__fdiv_rn(x.x, scale)), -127.0f), 127.0f);
            c.y = (int8_t)fminf(fmaxf(rintf(__fdiv_rn(x.y, scale)), -127.0f), 127.0f);
            c.z = (int8_t)fminf(fmaxf(rintf(__fdiv_rn(x.z, scale)), -127.0f), 127.0f);
            c.w = (int8_t)fminf(fmaxf(rintf(__fdiv_rn(x.w, scale)), -127.0f), 127.0f);
            dst[idx] = c;
        }
        return;
    }

    // ---- Q/K: [head][d][s] float -> [head][s][d] int8 (quant + transpose) ----
    const float* src = (z == 0) ? q : k;
    int8_t* dst = (z == 0) ? g_q8 : g_k8;
    const float amax = __uint_as_float(g_stat[z]);
    const float scale = fmaxf(__fdiv_rn(amax, 127.0f), 1e-8f);
    const int head = blockIdx.y;
    const int s0 = blockIdx.x * 64;
    #pragma unroll
    for (int i = 0; i < 4; i++) {
        int idx = i * 256 + t;
        int dd = idx >> 4;
        int sc = (idx & 15) * 4;
        float4 x = *(const float4*)&src[((size_t)(head * D + dd)) * S + s0 + sc];
        char4 c;
        c.x = (int8_t)fminf(fmaxf(rintf(__fdiv_rn(x.x, scale)), -127.0f), 127.0f);
        c.y = (int8_t)fminf(fmaxf(rintf(__fdiv_rn(x.y, scale)), -127.0f), 127.0f);
        c.z = (int8_t)fminf(fmaxf(rintf(__fdiv_rn(x.z, scale)), -127.0f), 127.0f);
        c.w = (int8_t)fminf(fmaxf(rintf(__fdiv_rn(x.w, scale)), -127.0f), 127.0f);
        *(char4*)&tile[dd][sc] = c;
    }
    __syncthreads();
    #pragma unroll
    for (int i = 0; i < 4; i++) {
        int ss = i * 16 + (t >> 4);
        int d4 = (t & 15) * 4;
        char4 c;
        c.x = tile[d4 + 0][ss]; c.y = tile[d4 + 1][ss];
        c.z = tile[d4 + 2][ss]; c.w = tile[d4 + 3][ss];
        *(char4*)&dst[((size_t)(head * S + s0 + ss)) * D + d4] = c;
    }
}

// ------------------------------------------------------------------
// Phase A: QK via IMMA + online softmax; store rden (=max prob) and row max.
// grid (8, 64), block 256 (8 warps x 16 rows = 128 Q rows per CTA)
__global__ __launch_bounds__(256) void k_phaseA() {
    const int head = blockIdx.y;
    const int s_blk = blockIdx.x * 128;
    const int tid = threadIdx.x;
    const int w = tid >> 5, lane = tid & 31;
    const int qr = lane >> 2, ql = lane & 3;

    __shared__ __align__(16) int Ksm[128 * 20];   // stride 80B, conflict-free

    int aq[2][4];
    {
        const int8_t* qb = g_q8 + ((size_t)(head * S + s_blk + w * 16)) * 64;
        #pragma unroll
        for (int ks = 0; ks < 2; ks++) {
            aq[ks][0] = *(const int*)(qb + qr * 64 + ks * 32 + ql * 4);
            aq[ks][1] = *(const int*)(qb + (qr + 8) * 64 + ks * 32 + ql * 4);
            aq[ks][2] = *(const int*)(qb + qr * 64 + ks * 32 + 16 + ql * 4);
            aq[ks][3] = *(const int*)(qb + (qr + 8) * 64 + ks * 32 + 16 + ql * 4);
        }
    }
    const float sq = fmaxf(__fdiv_rn(__uint_as_float(g_stat[0]), 127.0f), 1e-8f);
    const float sk = fmaxf(__fdiv_rn(__uint_as_float(g_stat[1]), 127.0f), 1e-8f);
    const float mult = sq * sk * 0.125f;

    float m0 = -3.4e38f, m1 = -3.4e38f, sum0 = 0.0f, sum1 = 0.0f;

    for (int ch = 0; ch < 8; ch++) {
        __syncthreads();
        const int* src = (const int*)(g_k8 + ((size_t)(head * S + ch * 128)) * 64);
        for (int i = tid; i < 2048; i += 256)
            Ksm[(i >> 4) * 20 + (i & 15)] = src[i];
        __syncthreads();

        int qa[16][4];
        #pragma unroll
        for (int nt = 0; nt < 16; nt++)
            qa[nt][0] = qa[nt][1] = qa[nt][2] = qa[nt][3] = 0;
        #pragma unroll
        for (int ks = 0; ks < 2; ks++) {
            #pragma unroll
            for (int nt = 0; nt < 16; nt++) {
                int base = (nt * 8 + qr) * 20 + ks * 8 + ql;
                imma(qa[nt], aq[ks], Ksm[base], Ksm[base + 4]);
            }
        }
        float cm0 = -3.4e38f, cm1 = -3.4e38f;
        #pragma unroll
        for (int nt = 0; nt < 16; nt++) {
            float l0 = (float)qa[nt][0] * mult; qa[nt][0] = __float_as_int(l0);
            float l1 = (float)qa[nt][1] * mult; qa[nt][1] = __float_as_int(l1);
            float l2 = (float)qa[nt][2] * mult; qa[nt][2] = __float_as_int(l2);
            float l3 = (float)qa[nt][3] * mult; qa[nt][3] = __float_as_int(l3);
            cm0 = fmaxf(cm0, fmaxf(l0, l1));
            cm1 = fmaxf(cm1, fmaxf(l2, l3));
        }
        cm0 = fmaxf(cm0, __shfl_xor_sync(0xffffffffu, cm0, 1));
        cm0 = fmaxf(cm0, __shfl_xor_sync(0xffffffffu, cm0, 2));
        cm1 = fmaxf(cm1, __shfl_xor_sync(0xffffffffu, cm1, 1));
        cm1 = fmaxf(cm1, __shfl_xor_sync(0xffffffffu, cm1, 2));
        float nm0 = fmaxf(m0, cm0), nm1 = fmaxf(m1, cm1);
        sum0 *= __expf(m0 - nm0);
        sum1 *= __expf(m1 - nm1);
        m0 = nm0; m1 = nm1;
        #pragma unroll
        for (int nt = 0; nt < 16; nt++) {
            sum0 += __expf(__int_as_float(qa[nt][0]) - m0);
            sum0 += __expf(__int_as_float(qa[nt][1]) - m0);
            sum1 += __expf(__int_as_float(qa[nt][2]) - m1);
            sum1 += __expf(__int_as_float(qa[nt][3]) - m1);
        }
    }
    sum0 += __shfl_xor_sync(0xffffffffu, sum0, 1);
    sum0 += __shfl_xor_sync(0xffffffffu, sum0, 2);
    sum1 += __shfl_xor_sync(0xffffffffu, sum1, 1);
    sum1 += __shfl_xor_sync(0xffffffffu, sum1, 2);
    const float rd0 = __frcp_rn(sum0);
    const float rd1 = __frcp_rn(sum1);
    if (ql == 0) {
        int r = head * S + s_blk + w * 16 + qr;
        g_rden[r] = rd0; g_rden[r + 8] = rd1;
        g_rmax[r] = m0;  g_rmax[r + 8] = m1;
    }
    float wm = fmaxf(rd0, rd1);
    wm = fmaxf(wm, __shfl_xor_sync(0xffffffffu, wm, 4));
    wm = fmaxf(wm, __shfl_xor_sync(0xffffffffu, wm, 8));
    wm = fmaxf(wm, __shfl_xor_sync(0xffffffffu, wm, 16));
    if (lane == 0) atomicMax(&g_stat[3], __float_as_uint(wm));
}

// ------------------------------------------------------------------
// Phase B: recompute QK (IMMA, identical ints) in two nt-halves (reg relief),
// softmax via stored m/rden, table double-quant -> smem P (s8) -> PV IMMA.
// grid (8, 64), block 256
#define SM_KS 0          // 128*20 ints (10240 B)
#define SM_VS 10240      // 64*36 ints  (9216 B)
#define SM_PS 19456      // 8 warps * 2304 B  (16 rows x 144 B)
#define SM_TOT 37888     // Osm (64*132 floats = 33792 B) aliases from 0
__global__ __launch_bounds__(256) void k_phaseB(float* __restrict__ out) {
    __shared__ __align__(16) char sm[SM_TOT];
    __shared__ unsigned char k2tab[256];

    const int head = blockIdx.y;
    const int s_blk = blockIdx.x * 128;
    const int tid = threadIdx.x;
    const int w = tid >> 5, lane = tid & 31;
    const int qr = lane >> 2, ql = lane & 3;

    const float maxp = __uint_as_float(g_stat[3]);
    const float s1 = fmaxf(__fdiv_rn(maxp, 255.0f), 1e-8f);
    const float s2 = fmaxf(__fdiv_rn(255.0f * s1, 127.0f), 1e-8f);
    const float sv = fmaxf(__fdiv_rn(__uint_as_float(g_stat[2]), 127.0f), 1e-8f);
    const float r1s = __fdiv_rn(1.0f, s1);
    if (tid < 256) {
        float cq = (float)tid * s1;
        float k2 = fminf(fmaxf(rintf(__fdiv_rn(cq, s2)), 0.0f), 127.0f);
        k2tab[tid] = (unsigned char)(int)k2;
    }

    int aq[2][4];
    {
        const int8_t* qb = g_q8 + ((size_t)(head * S + s_blk + w * 16)) * 64;
        #pragma unroll
        for (int ks = 0; ks < 2; ks++) {
            aq[ks][0] = *(const int*)(qb + qr * 64 + ks * 32 + ql * 4);
            aq[ks][1] = *(const int*)(qb + (qr + 8) * 64 + ks * 32 + ql * 4);
            aq[ks][2] = *(const int*)(qb + qr * 64 + ks * 32 + 16 + ql * 4);
            aq[ks][3] = *(const int*)(qb + (qr + 8) * 64 + ks * 32 + 16 + ql * 4);
        }
    }
    const float sq = fmaxf(__fdiv_rn(__uint_as_float(g_stat[0]), 127.0f), 1e-8f);
    const float sk = fmaxf(__fdiv_rn(__uint_as_float(g_stat[1]), 127.0f), 1e-8f);
    const float mult = sq * sk * 0.125f;

    const int rbase = head * S + s_blk + w * 16 + qr;
    const float m_lo = g_rmax[rbase],     m_hi = g_rmax[rbase + 8];
    const float rd_lo = g_rden[rbase],    rd_hi = g_rden[rbase + 8];

    int* KsmI = (int*)(sm + SM_KS);
    int* VsmI = (int*)(sm + SM_VS);
    char* PsmW = sm + SM_PS + w * 2304;

    int pacc[8][4];
    #pragma unroll
    for (int nt = 0; nt < 8; nt++)
        pacc[nt][0] = pacc[nt][1] = pacc[nt][2] = pacc[nt][3] = 0;

    const int* ksrc0 = (const int*)(g_k8 + ((size_t)head * S) * 64);
    const int* vsrc0 = (const int*)g_v8 + head * (D * S / 4);

    for (int ch = 0; ch < 8; ch++) {
        __syncthreads();
        const int* ks_src = ksrc0 + ch * 128 * 16;
        for (int i = tid; i < 2048; i += 256)
            KsmI[(i >> 4) * 20 + (i & 15)] = ks_src[i];
        for (int i = tid; i < 2048; i += 256) {
            int dd = i >> 5, wd = i & 31;
            VsmI[dd * 36 + wd] = vsrc0[dd * 256 + ch * 32 + wd];
        }
        __syncthreads();

        // ---- QK + softmax + double-quant, two halves of 8 n-tiles ----
        #pragma unroll
        for (int half = 0; half < 2; half++) {
            int qa[8][4];
            #pragma unroll
            for (int nt = 0; nt < 8; nt++)
                qa[nt][0] = qa[nt][1] = qa[nt][2] = qa[nt][3] = 0;
            #pragma unroll
            for (int ks = 0; ks < 2; ks++) {
                #pragma unroll
                for (int nt = 0; nt < 8; nt++) {
                    int base = ((half * 8 + nt) * 8 + qr) * 20 + ks * 8 + ql;
                    imma(qa[nt], aq[ks], KsmI[base], KsmI[base + 4]);
                }
            }
            #pragma unroll
            for (int nt = 0; nt < 8; nt++) {
                float p0 = __expf((float)qa[nt][0] * mult - m_lo) * rd_lo;
                float p1 = __expf((float)qa[nt][1] * mult - m_lo) * rd_lo;
                float p2 = __expf((float)qa[nt][2] * mult - m_hi) * rd_hi;
                float p3 = __expf((float)qa[nt][3] * mult - m_hi) * rd_hi;
                int i0 = min(__float2int_rn(p0 * r1s), 255);
                int i1 = min(__float2int_rn(p1 * r1s), 255);
                int i2 = min(__float2int_rn(p2 * r1s), 255);
                int i3 = min(__float2int_rn(p3 * r1s), 255);
                int col = (half * 8 + nt) * 8 + ql * 2;
                *(uint16_t*)(PsmW + qr * 144 + col) =
                    (uint16_t)(k2tab[i0] | ((uint16_t)k2tab[i1] << 8));
                *(uint16_t*)(PsmW + (qr + 8) * 144 + col) =
                    (uint16_t)(k2tab[i2] | ((uint16_t)k2tab[i3] << 8));
            }
        }
        __syncwarp();
        // ---- PV ----
        #pragma unroll
        for (int ks = 0; ks < 4; ks++) {
            int pa[4];
            pa[0] = *(const int*)(PsmW + qr * 144 + ks * 32 + ql * 4);
            pa[1] = *(const int*)(PsmW + (qr + 8) * 144 + ks * 32 + ql * 4);
            pa[2] = *(const int*)(PsmW + qr * 144 + ks * 32 + 16 + ql * 4);
            pa[3] = *(const int*)(PsmW + (qr + 8) * 144 + ks * 32 + 16 + ql * 4);
            #pragma unroll
            for (int nt = 0; nt < 8; nt++) {
                int base = (nt * 8 + qr) * 36 + ks * 8 + ql;
                imma(pacc[nt], pa, VsmI[base], VsmI[base + 4]);
            }
        }
    }

    // ---- epilogue: smem transpose then coalesced store ----
    __syncthreads();
    float* Osm = (float*)sm;
    const float fs = s2 * sv;
    #pragma unroll
    for (int nt = 0; nt < 8; nt++) {
        int d0 = nt * 8 + ql * 2;
        int s_lo = w * 16 + qr;
        Osm[d0 * 132 + s_lo]            = (float)pacc[nt][0] * fs;
        Osm[(d0 + 1) * 132 + s_lo]      = (float)pacc[nt][1] * fs;
        Osm[d0 * 132 + s_lo + 8]        = (float)pacc[nt][2] * fs;
        Osm[(d0 + 1) * 132 + s_lo + 8]  = (float)pacc[nt][3] * fs;
    }
    __syncthreads();
    int dd = tid >> 2;
    int sseg = (tid & 3) * 32;
    float* orow = out + ((size_t)(head * D + dd)) * S + s_blk + sseg;
    #pragma unroll
    for (int i = 0; i < 8; i++)
        *(float4*)(orow + i * 4) = *(float4*)&Osm[dd * 132 + sseg + i * 4];
}

// ------------------------------------------------------------------
extern "C" void kernel_launch(void* const* d_in, const int* in_sizes, int n_in,
                              void* d_out, int out_size) {
    (void)in_sizes; (void)n_in; (void)out_size;
    const float* q = (const float*)d_in[0];
    const float* k = (const float*)d_in[1];
    const float* v = (const float*)d_in[2];
    float* out = (float*)d_out;

    k_init<<<1, 1>>>();
    k_absmax<<<dim3(148, 3), 256>>>(q, k, v);
    k_quant<<<dim3(16, HEADS, 3), 256>>>(q, k, v);
    k_phaseA<<<dim3(8, HEADS), 256>>>();
    k_phaseB<<<dim3(8, HEADS), 256>>>(out);
}

// round 12
// speedup vs baseline: 2.3906x; 1.1072x over previous
#include <cuda_runtime.h>
#include <cstdint>

#define BATCH 16
#define NH 4
#define HEADS (BATCH*NH)      // 64
#define D 64
#define S 1024
#define NELEM (HEADS*D*S)     // 4194304 per tensor

// ---- scratch (device globals; no runtime allocation) ----
__device__ int8_t  g_q8[HEADS*S*D];            // [head][s][d]  4MB
__device__ int8_t  g_k8[HEADS*S*D];            // [head][t][d]  4MB
__device__ int8_t  g_v8[HEADS*D*S];            // [head][d][t]  4MB
__device__ float   g_rden[HEADS*S];            // 1/denominator per row
__device__ float   g_rmax[HEADS*S];            // row max logit
__device__ unsigned g_stat[4];                  // absmax bits: q,k,v ; maxprob bits

// ------------------------------------------------------------------
__device__ __forceinline__ void imma(int* c, const int* a, int b0, int b1) {
    asm volatile(
        "mma.sync.aligned.m16n8k32.row.col.s32.s8.s8.s32 "
        "{%0,%1,%2,%3}, {%4,%5,%6,%7}, {%8,%9}, {%0,%1,%2,%3};\n"
        : "+r"(c[0]), "+r"(c[1]), "+r"(c[2]), "+r"(c[3])
        : "r"(a[0]), "r"(a[1]), "r"(a[2]), "r"(a[3]), "r"(b0), "r"(b1));
}

// ------------------------------------------------------------------
__global__ void k_init() {
    g_stat[0] = 0u; g_stat[1] = 0u; g_stat[2] = 0u; g_stat[3] = 0u;
}

// ------------------------------------------------------------------
__global__ void k_absmax(const float* __restrict__ q,
                         const float* __restrict__ k,
                         const float* __restrict__ v) {
    const float* p = (blockIdx.y == 0) ? q : ((blockIdx.y == 1) ? k : v);
    const float4* p4 = (const float4*)p;
    const int n4 = NELEM / 4;
    float m = 0.0f;
    for (int i = blockIdx.x * blockDim.x + threadIdx.x; i < n4;
         i += gridDim.x * blockDim.x) {
        float4 x = p4[i];
        m = fmaxf(m, fmaxf(fmaxf(fabsf(x.x), fabsf(x.y)),
                           fmaxf(fabsf(x.z), fabsf(x.w))));
    }
    #pragma unroll
    for (int o = 16; o; o >>= 1) m = fmaxf(m, __shfl_xor_sync(0xffffffffu, m, o));
    __shared__ float sm[8];
    if ((threadIdx.x & 31) == 0) sm[threadIdx.x >> 5] = m;
    __syncthreads();
    if (threadIdx.x == 0) {
        float t = sm[0];
        #pragma unroll
        for (int w = 1; w < 8; w++) t = fmaxf(t, sm[w]);
        atomicMax(&g_stat[blockIdx.y], __float_as_uint(t));
    }
}

// ------------------------------------------------------------------
// One launch for all quantization.
// z=0: Q transpose-quant, z=1: K transpose-quant, z=2: V in-layout quant.
// grid (16, 64, 3), block 256
__global__ void k_quant(const float* __restrict__ q, const float* __restrict__ k,
                        const float* __restrict__ v) {
    const int z = blockIdx.z;
    __shared__ int8_t tile[64][68];
    const int t = threadIdx.x;

    if (z == 2) {   // ---- V: [head][d][t] float -> int8, same layout ----
        const float amax = __uint_as_float(g_stat[2]);
        const float scale = fmaxf(__fdiv_rn(amax, 127.0f), 1e-8f);
        const int wrp = (blockIdx.y * 16 + blockIdx.x) * 8 + (t >> 5);  // 0..8191
        const int row = wrp >> 1;
        const int half = wrp & 1;
        const int lane = t & 31;
        const float4* src = (const float4*)(v + (size_t)row * S + half * (S / 2));
        char4* dst = (char4*)(g_v8 + (size_t)row * S + half * (S / 2));
        #pragma unroll
        for (int i = 0; i < 4; i++) {
            int idx = lane + 32 * i;
            float4 x = src[idx];
            char4 c;
            c.x = (int8_t)fminf(fmaxf(rintf(__fdiv_rn(x.x, scale)), -127.0f), 127.0f);
            c.y = (int8_t)fminf(fmaxf(rintf(__fdiv_rn(x.y, scale)), -127.0f), 127.0f);
            c.z = (int8_t)fminf(fmaxf(rintf(__fdiv_rn(x.z, scale)), -127.0f), 127.0f);
            c.w = (int8_t)fminf(fmaxf(rintf(__fdiv_rn(x.w, scale)), -127.0f), 127.0f);
            dst[idx] = c;
        }
        return;
    }

    // ---- Q/K: [head][d][s] float -> [head][s][d] int8 (quant + transpose) ----
    const float* src = (z == 0) ? q : k;
    int8_t* dst = (z == 0) ? g_q8 : g_k8;
    const float amax = __uint_as_float(g_stat[z]);
    const float scale = fmaxf(__fdiv_rn(amax, 127.0f), 1e-8f);
    const int head = blockIdx.y;
    const int s0 = blockIdx.x * 64;
    #pragma unroll
    for (int i = 0; i < 4; i++) {
        int idx = i * 256 + t;
        int dd = idx >> 4;
        int sc = (idx & 15) * 4;
        float4 x = *(const float4*)&src[((size_t)(head * D + dd)) * S + s0 + sc];
        char4 c;
        c.x = (int8_t)fminf(fmaxf(rintf(__fdiv_rn(x.x, scale)), -127.0f), 127.0f);
        c.y = (int8_t)fminf(fmaxf(rintf(__fdiv_rn(x.y, scale)), -127.0f), 127.0f);
        c.z = (int8_t)fminf(fmaxf(rintf(__fdiv_rn(x.z, scale)), -127.0f), 127.0f);
        c.w = (int8_t)fminf(fmaxf(rintf(__fdiv_rn(x.w, scale)), -127.0f), 127.0f);
        *(char4*)&tile[dd][sc] = c;
    }
    __syncthreads();
    #pragma unroll
    for (int i = 0; i < 4; i++) {
        int ss = i * 16 + (t >> 4);
        int d4 = (t & 15) * 4;
        char4 c;
        c.x = tile[d4 + 0][ss]; c.y = tile[d4 + 1][ss];
        c.z = tile[d4 + 2][ss]; c.w = tile[d4 + 3][ss];
        *(char4*)&dst[((size_t)(head * S + s0 + ss)) * D + d4] = c;
    }
}

// ------------------------------------------------------------------
// Phase A: QK via IMMA + online softmax; store rden (=max prob) and row max.
// 128-thread CTAs (4 warps x 16 rows = 64 Q rows) so 4+ independent CTAs/SM
// desynchronize and keep the tensor pipe fed.  grid (16, 64)
__global__ __launch_bounds__(128) void k_phaseA() {
    const int head = blockIdx.y;
    const int s_blk = blockIdx.x * 64;
    const int tid = threadIdx.x;
    const int w = tid >> 5, lane = tid & 31;
    const int qr = lane >> 2, ql = lane & 3;

    __shared__ __align__(16) int Ksm[128 * 20];   // stride 80B, conflict-free

    int aq[2][4];
    {
        const int8_t* qb = g_q8 + ((size_t)(head * S + s_blk + w * 16)) * 64;
        #pragma unroll
        for (int ks = 0; ks < 2; ks++) {
            aq[ks][0] = *(const int*)(qb + qr * 64 + ks * 32 + ql * 4);
            aq[ks][1] = *(const int*)(qb + (qr + 8) * 64 + ks * 32 + ql * 4);
            aq[ks][2] = *(const int*)(qb + qr * 64 + ks * 32 + 16 + ql * 4);
            aq[ks][3] = *(const int*)(qb + (qr + 8) * 64 + ks * 32 + 16 + ql * 4);
        }
    }
    const float sq = fmaxf(__fdiv_rn(__uint_as_float(g_stat[0]), 127.0f), 1e-8f);
    const float sk = fmaxf(__fdiv_rn(__uint_as_float(g_stat[1]), 127.0f), 1e-8f);
    const float mult = sq * sk * 0.125f;

    float m0 = -3.4e38f, m1 = -3.4e38f, sum0 = 0.0f, sum1 = 0.0f;

    for (int ch = 0; ch < 8; ch++) {
        __syncthreads();
        const int* src = (const int*)(g_k8 + ((size_t)(head * S + ch * 128)) * 64);
        for (int i = tid; i < 2048; i += 128)
            Ksm[(i >> 4) * 20 + (i & 15)] = src[i];
        __syncthreads();

        int qa[16][4];
        #pragma unroll
        for (int nt = 0; nt < 16; nt++)
            qa[nt][0] = qa[nt][1] = qa[nt][2] = qa[nt][3] = 0;
        #pragma unroll
        for (int ks = 0; ks < 2; ks++) {
            #pragma unroll
            for (int nt = 0; nt < 16; nt++) {
                int base = (nt * 8 + qr) * 20 + ks * 8 + ql;
                imma(qa[nt], aq[ks], Ksm[base], Ksm[base + 4]);
            }
        }
        float cm0 = -3.4e38f, cm1 = -3.4e38f;
        #pragma unroll
        for (int nt = 0; nt < 16; nt++) {
            float l0 = (float)qa[nt][0] * mult; qa[nt][0] = __float_as_int(l0);
            float l1 = (float)qa[nt][1] * mult; qa[nt][1] = __float_as_int(l1);
            float l2 = (float)qa[nt][2] * mult; qa[nt][2] = __float_as_int(l2);
            float l3 = (float)qa[nt][3] * mult; qa[nt][3] = __float_as_int(l3);
            cm0 = fmaxf(cm0, fmaxf(l0, l1));
            cm1 = fmaxf(cm1, fmaxf(l2, l3));
        }
        cm0 = fmaxf(cm0, __shfl_xor_sync(0xffffffffu, cm0, 1));
        cm0 = fmaxf(cm0, __shfl_xor_sync(0xffffffffu, cm0, 2));
        cm1 = fmaxf(cm1, __shfl_xor_sync(0xffffffffu, cm1, 1));
        cm1 = fmaxf(cm1, __shfl_xor_sync(0xffffffffu, cm1, 2));
        float nm0 = fmaxf(m0, cm0), nm1 = fmaxf(m1, cm1);
        sum0 *= __expf(m0 - nm0);
        sum1 *= __expf(m1 - nm1);
        m0 = nm0; m1 = nm1;
        #pragma unroll
        for (int nt = 0; nt < 16; nt++) {
            sum0 += __expf(__int_as_float(qa[nt][0]) - m0);
            sum0 += __expf(__int_as_float(qa[nt][1]) - m0);
            sum1 += __expf(__int_as_float(qa[nt][2]) - m1);
            sum1 += __expf(__int_as_float(qa[nt][3]) - m1);
        }
    }
    sum0 += __shfl_xor_sync(0xffffffffu, sum0, 1);
    sum0 += __shfl_xor_sync(0xffffffffu, sum0, 2);
    sum1 += __shfl_xor_sync(0xffffffffu, sum1, 1);
    sum1 += __shfl_xor_sync(0xffffffffu, sum1, 2);
    const float rd0 = __frcp_rn(sum0);
    const float rd1 = __frcp_rn(sum1);
    if (ql == 0) {
        int r = head * S + s_blk + w * 16 + qr;
        g_rden[r] = rd0; g_rden[r + 8] = rd1;
        g_rmax[r] = m0;  g_rmax[r + 8] = m1;
    }
    float wm = fmaxf(rd0, rd1);
    wm = fmaxf(wm, __shfl_xor_sync(0xffffffffu, wm, 4));
    wm = fmaxf(wm, __shfl_xor_sync(0xffffffffu, wm, 8));
    wm = fmaxf(wm, __shfl_xor_sync(0xffffffffu, wm, 16));
    if (lane == 0) atomicMax(&g_stat[3], __float_as_uint(wm));
}

// ------------------------------------------------------------------
// Phase B: recompute QK (IMMA, identical ints) in two nt-halves,
// softmax via stored m/rden, table double-quant -> smem P (s8) -> PV IMMA.
// 128-thread CTAs (64 Q rows), grid (16, 64)
#define SM_KS 0          // 128*20 ints (10240 B)
#define SM_VS 10240      // 64*36 ints  (9216 B)
#define SM_PS 19456      // 4 warps * 2304 B  (16 rows x 144 B)
#define SM_TOT 28672     // Osm (64*68 floats = 17408 B) aliases from 0
__global__ __launch_bounds__(128) void k_phaseB(float* __restrict__ out) {
    __shared__ __align__(16) char sm[SM_TOT];
    __shared__ unsigned char k2tab[256];

    const int head = blockIdx.y;
    const int s_blk = blockIdx.x * 64;
    const int tid = threadIdx.x;
    const int w = tid >> 5, lane = tid & 31;
    const int qr = lane >> 2, ql = lane & 3;

    const float maxp = __uint_as_float(g_stat[3]);
    const float s1 = fmaxf(__fdiv_rn(maxp, 255.0f), 1e-8f);
    const float s2 = fmaxf(__fdiv_rn(255.0f * s1, 127.0f), 1e-8f);
    const float sv = fmaxf(__fdiv_rn(__uint_as_float(g_stat[2]), 127.0f), 1e-8f);
    const float r1s = __fdiv_rn(1.0f, s1);
    for (int i = tid; i < 256; i += 128) {
        float cq = (float)i * s1;
        float k2 = fminf(fmaxf(rintf(__fdiv_rn(cq, s2)), 0.0f), 127.0f);
        k2tab[i] = (unsigned char)(int)k2;
    }

    int aq[2][4];
    {
        const int8_t* qb = g_q8 + ((size_t)(head * S + s_blk + w * 16)) * 64;
        #pragma unroll
        for (int ks = 0; ks < 2; ks++) {
            aq[ks][0] = *(const int*)(qb + qr * 64 + ks * 32 + ql * 4);
            aq[ks][1] = *(const int*)(qb + (qr + 8) * 64 + ks * 32 + ql * 4);
            aq[ks][2] = *(const int*)(qb + qr * 64 + ks * 32 + 16 + ql * 4);
            aq[ks][3] = *(const int*)(qb + (qr + 8) * 64 + ks * 32 + 16 + ql * 4);
        }
    }
    const float sq = fmaxf(__fdiv_rn(__uint_as_float(g_stat[0]), 127.0f), 1e-8f);
    const float sk = fmaxf(__fdiv_rn(__uint_as_float(g_stat[1]), 127.0f), 1e-8f);
    const float mult = sq * sk * 0.125f;

    const int rbase = head * S + s_blk + w * 16 + qr;
    const float m_lo = g_rmax[rbase],     m_hi = g_rmax[rbase + 8];
    const float rd_lo = g_rden[rbase],    rd_hi = g_rden[rbase + 8];

    int* KsmI = (int*)(sm + SM_KS);
    int* VsmI = (int*)(sm + SM_VS);
    char* PsmW = sm + SM_PS + w * 2304;

    int pacc[8][4];
    #pragma unroll
    for (int nt = 0; nt < 8; nt++)
        pacc[nt][0] = pacc[nt][1] = pacc[nt][2] = pacc[nt][3] = 0;

    const int* ksrc0 = (const int*)(g_k8 + ((size_t)head * S) * 64);
    const int* vsrc0 = (const int*)g_v8 + head * (D * S / 4);

    for (int ch = 0; ch < 8; ch++) {
        __syncthreads();
        const int* ks_src = ksrc0 + ch * 128 * 16;
        for (int i = tid; i < 2048; i += 128)
            KsmI[(i >> 4) * 20 + (i & 15)] = ks_src[i];
        for (int i = tid; i < 2048; i += 128) {
            int dd = i >> 5, wd = i & 31;
            VsmI[dd * 36 + wd] = vsrc0[dd * 256 + ch * 32 + wd];
        }
        __syncthreads();

        // ---- QK + softmax + double-quant, two halves of 8 n-tiles ----
        #pragma unroll
        for (int half = 0; half < 2; half++) {
            int qa[8][4];
            #pragma unroll
            for (int nt = 0; nt < 8; nt++)
                qa[nt][0] = qa[nt][1] = qa[nt][2] = qa[nt][3] = 0;
            #pragma unroll
            for (int ks = 0; ks < 2; ks++) {
                #pragma unroll
                for (int nt = 0; nt < 8; nt++) {
                    int base = ((half * 8 + nt) * 8 + qr) * 20 + ks * 8 + ql;
                    imma(qa[nt], aq[ks], KsmI[base], KsmI[base + 4]);
                }
            }
            #pragma unroll
            for (int nt = 0; nt < 8; nt++) {
                float p0 = __expf((float)qa[nt][0] * mult - m_lo) * rd_lo;
                float p1 = __expf((float)qa[nt][1] * mult - m_lo) * rd_lo;
                float p2 = __expf((float)qa[nt][2] * mult - m_hi) * rd_hi;
                float p3 = __expf((float)qa[nt][3] * mult - m_hi) * rd_hi;
                int i0 = min(__float2int_rn(p0 * r1s), 255);
                int i1 = min(__float2int_rn(p1 * r1s), 255);
                int i2 = min(__float2int_rn(p2 * r1s), 255);
                int i3 = min(__float2int_rn(p3 * r1s), 255);
                int col = (half * 8 + nt) * 8 + ql * 2;
                *(uint16_t*)(PsmW + qr * 144 + col) =
                    (uint16_t)(k2tab[i0] | ((uint16_t)k2tab[i1] << 8));
                *(uint16_t*)(PsmW + (qr + 8) * 144 + col) =
                    (uint16_t)(k2tab[i2] | ((uint16_t)k2tab[i3] << 8));
            }
        }
        __syncwarp();
        // ---- PV ----
        #pragma unroll
        for (int ks = 0; ks < 4; ks++) {
            int pa[4];
            pa[0] = *(const int*)(PsmW + qr * 144 + ks * 32 + ql * 4);
            pa[1] = *(const int*)(PsmW + (qr + 8) * 144 + ks * 32 + ql * 4);
            pa[2] = *(const int*)(PsmW + qr * 144 + ks * 32 + 16 + ql * 4);
            pa[3] = *(const int*)(PsmW + (qr + 8) * 144 + ks * 32 + 16 + ql * 4);
            #pragma unroll
            for (int nt = 0; nt < 8; nt++) {
                int base = (nt * 8 + qr) * 36 + ks * 8 + ql;
                imma(pacc[nt], pa, VsmI[base], VsmI[base + 4]);
            }
        }
    }

    // ---- epilogue: smem transpose then coalesced store ----
    __syncthreads();
    float* Osm = (float*)sm;
    const float fs = s2 * sv;
    #pragma unroll
    for (int nt = 0; nt < 8; nt++) {
        int d0 = nt * 8 + ql * 2;
        int s_lo = w * 16 + qr;
        Osm[d0 * 68 + s_lo]            = (float)pacc[nt][0] * fs;
        Osm[(d0 + 1) * 68 + s_lo]      = (float)pacc[nt][1] * fs;
        Osm[d0 * 68 + s_lo + 8]        = (float)pacc[nt][2] * fs;
        Osm[(d0 + 1) * 68 + s_lo + 8]  = (float)pacc[nt][3] * fs;
    }
    __syncthreads();
    int dd = tid >> 1;
    int sseg = (tid & 1) * 32;
    float* orow = out + ((size_t)(head * D + dd)) * S + s_blk + sseg;
    #pragma unroll
    for (int i = 0; i < 8; i++)
        *(float4*)(orow + i * 4) = *(float4*)&Osm[dd * 68 + sseg + i * 4];
}

// ------------------------------------------------------------------
extern "C" void kernel_launch(void* const* d_in, const int* in_sizes, int n_in,
                              void* d_out, int out_size) {
    (void)in_sizes; (void)n_in; (void)out_size;
    const float* q = (const float*)d_in[0];
    const float* k = (const float*)d_in[1];
    const float* v = (const float*)d_in[2];
    float* out = (float*)d_out;

    k_init<<<1, 1>>>();
    k_absmax<<<dim3(148, 3), 256>>>(q, k, v);
    k_quant<<<dim3(16, HEADS, 3), 256>>>(q, k, v);
    k_phaseA<<<dim3(16, HEADS), 128>>>();
    k_phaseB<<<dim3(16, HEADS), 128>>>(out);
}